// round 3
// baseline (speedup 1.0000x reference)
#include <cuda_runtime.h>
#include <math.h>

#define Bc 16
#define Lc 4096
#define Hc 256
#define Nc 32
#define DINc 257
#define DOUTc 257
#define NLc 4
#define BHLc (Bc*Hc*Lc)

__device__ float  g_xr[BHLc];
__device__ float  g_xi[BHLc];
__device__ float  g_conv[4*BHLc];
__device__ float  g_encT[2][DINc*Hc];
__device__ float  g_decT[2][Hc*DOUTc];
__device__ float  g_woutT[8*131072];
__device__ float4 g_coef[NLc*2*Hc*Nc];

typedef unsigned long long u64;

__device__ __forceinline__ u64 pack2(float v){ u64 r; asm("mov.b64 %0, {%1, %1};" : "=l"(r) : "f"(v)); return r; }
__device__ __forceinline__ u64 pk(float a, float b){ u64 r; asm("mov.b64 %0, {%1, %2};" : "=l"(r) : "f"(a), "f"(b)); return r; }
__device__ __forceinline__ u64 fma2(u64 a, u64 b, u64 c){ u64 d; asm("fma.rn.f32x2 %0, %1, %2, %3;" : "=l"(d) : "l"(a), "l"(b), "l"(c)); return d; }
__device__ __forceinline__ u64 mul2(u64 a, u64 b){ u64 d; asm("mul.rn.f32x2 %0, %1, %2;" : "=l"(d) : "l"(a), "l"(b)); return d; }
__device__ __forceinline__ float2 upk(u64 v){ float2 r; asm("mov.b64 {%0, %1}, %2;" : "=f"(r.x), "=f"(r.y) : "l"(v)); return r; }

// ---------- prep ----------
__global__ void k_prep_enc(const float* __restrict__ Wr, const float* __restrict__ Wi){
    for (int i = blockIdx.x*blockDim.x + threadIdx.x; i < DINc*Hc; i += gridDim.x*blockDim.x){
        int d = i >> 8, h = i & 255;
        g_encT[0][i] = Wr[h*DINc + d];
        g_encT[1][i] = Wi[h*DINc + d];
    }
}
__global__ void k_prep_dec(const float* __restrict__ Wr, const float* __restrict__ Wi){
    for (int i = blockIdx.x*blockDim.x + threadIdx.x; i < Hc*DOUTc; i += gridDim.x*blockDim.x){
        int h = i / DOUTc, o = i % DOUTc;
        g_decT[0][i] = Wr[o*Hc + h];
        g_decT[1][i] = Wi[o*Hc + h];
    }
}
__global__ void k_prep_wout(const float* __restrict__ W){
    for (int i = blockIdx.x*blockDim.x + threadIdx.x; i < 8*131072; i += gridDim.x*blockDim.x){
        int lj = i >> 17, r = i & 131071;
        int hp = r >> 9, o = r & 511;
        g_woutT[i] = W[lj*131072 + o*256 + hp];
    }
}
__global__ void k_coef(const float* __restrict__ log_dt, const float* __restrict__ logAr,
                       const float* __restrict__ Aim, const float* __restrict__ C2){
    int t = blockIdx.x*blockDim.x + threadIdx.x;
    if (t >= NLc*2*Hc*Nc) return;
    int n = t & 31, h = (t >> 5) & 255, lj = t >> 13;
    double dt = exp((double)log_dt[lj*256 + h]);
    int idx = (lj*256 + h)*32 + n;
    double Ar = -exp((double)logAr[idx]);
    double Ai = (double)Aim[idx];
    double dAr = dt*Ar, dAi = dt*Ai;
    double er = exp(dAr);
    double wr = er*cos(dAi), wi = er*sin(dAi);
    double den = Ar*Ar + Ai*Ai;
    double nr = wr - 1.0, ni = wi;
    double Fr = (nr*Ar + ni*Ai)/den;
    double Fi = (ni*Ar - nr*Ai)/den;
    double Cr = (double)C2[idx*2], Ci = (double)C2[idx*2+1];
    g_coef[idx] = make_float4((float)wr, (float)wi,
                              (float)( 2.0*(Cr*Fr - Ci*Fi)),
                              (float)(-2.0*(Cr*Fi + Ci*Fr)));
}

// ---------- encoder: (B,L,257,2) -> g_xr/g_xi (B,H,L) ----------
__global__ __launch_bounds__(256) void k_encoder(const float* __restrict__ x,
                                                 const float* __restrict__ br,
                                                 const float* __restrict__ bi){
    __shared__ __align__(16) float xsr[DINc*16];
    __shared__ __align__(16) float xsi[DINc*16];
    int b = blockIdx.x >> 8;
    int l0 = (blockIdx.x & 255) << 4;
    int tid = threadIdx.x;
    const float* xb = x + ((long long)(b*Lc + l0))*DINc*2;
    for (int i = tid; i < 16*DINc*2; i += 256){
        int t = i / (DINc*2), dd = i % (DINc*2);
        float v = xb[i];
        if (dd & 1) xsi[(dd>>1)*16 + t] = v; else xsr[(dd>>1)*16 + t] = v;
    }
    __syncthreads();
    int h = tid;
    u64 yr[8], yi[8];
    #pragma unroll
    for (int p = 0; p < 8; ++p){ yr[p] = 0ull; yi[p] = 0ull; }
    for (int d = 0; d < DINc; ++d){
        u64 wr2 = pack2(g_encT[0][d*256 + h]);
        float wif = g_encT[1][d*256 + h];
        u64 wi2 = pack2(wif), nwi2 = pack2(-wif);
        const ulonglong2* xr4 = (const ulonglong2*)&xsr[d*16];
        const ulonglong2* xi4 = (const ulonglong2*)&xsi[d*16];
        #pragma unroll
        for (int j = 0; j < 4; ++j){
            ulonglong2 xr = xr4[j], xi = xi4[j];
            yr[2*j]   = fma2(wr2, xr.x, yr[2*j]);   yr[2*j]   = fma2(nwi2, xi.x, yr[2*j]);
            yi[2*j]   = fma2(wi2, xr.x, yi[2*j]);   yi[2*j]   = fma2(wr2,  xi.x, yi[2*j]);
            yr[2*j+1] = fma2(wr2, xr.y, yr[2*j+1]); yr[2*j+1] = fma2(nwi2, xi.y, yr[2*j+1]);
            yi[2*j+1] = fma2(wi2, xr.y, yi[2*j+1]); yi[2*j+1] = fma2(wr2,  xi.y, yi[2*j+1]);
        }
    }
    float brv = br[h], biv = bi[h];
    float2* pr = (float2*)&g_xr[(b*Hc + h)*Lc + l0];
    float2* pi = (float2*)&g_xi[(b*Hc + h)*Lc + l0];
    #pragma unroll
    for (int p = 0; p < 8; ++p){
        float2 a = upk(yr[p]), c = upk(yi[p]);
        pr[p] = make_float2(a.x + brv, a.y + brv);
        pi[p] = make_float2(c.x + biv, c.y + biv);
    }
}

// ---------- S4D scan: 4 evals, 4 threads/(b,h), 4 packed mode-pairs/thread ----------
__global__ __launch_bounds__(128) void k_scan(int layer, const float* __restrict__ s4D){
    int e = blockIdx.x >> 7;
    int bhb = blockIdx.x & 127;
    int tid = threadIdx.x;
    int g = tid >> 2, q = tid & 3;
    int bh = bhb*32 + g;
    int h = bh & 255;
    int jb = e & 1;
    const float* u = ((e == 0 || e == 3) ? g_xr : g_xi) + bh*Lc;
    float* outp = g_conv + e*BHLc + bh*Lc;

    u64 wr2[4], wi2[4], nwi2[4], kr2[4], ki2[4], sr2[4], si2[4];
    int cbase = ((layer*2 + jb)*256 + h)*32 + q*8;
    #pragma unroll
    for (int m = 0; m < 4; ++m){
        float4 c0 = g_coef[cbase + 2*m];
        float4 c1 = g_coef[cbase + 2*m + 1];
        wr2[m] = pk(c0.x, c1.x);
        wi2[m] = pk(c0.y, c1.y);
        nwi2[m] = pk(-c0.y, -c1.y);
        kr2[m] = pk(c0.z, c1.z);
        ki2[m] = pk(c0.w, c1.w);
        sr2[m] = 0ull; si2[m] = 0ull;
    }
    float Dv = s4D[(layer*2 + jb)*256 + h];

    for (int l = 0; l < Lc; l += 4){
        float4 uv = *(const float4*)(u + l);
        float us[4] = {uv.x, uv.y, uv.z, uv.w};
        float cc[4];
        #pragma unroll
        for (int s = 0; s < 4; ++s){
            u64 u2 = pack2(us[s]), c2 = 0ull;
            #pragma unroll
            for (int m = 0; m < 4; ++m){
                u64 t0 = fma2(wr2[m], sr2[m], u2);
                t0 = fma2(nwi2[m], si2[m], t0);
                u64 t1 = mul2(wr2[m], si2[m]);
                t1 = fma2(wi2[m], sr2[m], t1);
                sr2[m] = t0; si2[m] = t1;
                c2 = fma2(kr2[m], t0, c2);
                c2 = fma2(ki2[m], t1, c2);
            }
            float2 cf = upk(c2);
            float c = cf.x + cf.y;
            c += __shfl_xor_sync(0xffffffffu, c, 1);
            c += __shfl_xor_sync(0xffffffffu, c, 2);
            cc[s] = fmaf(Dv, us[s], c);
        }
        if (q == 0) *(float4*)(outp + l) = make_float4(cc[0], cc[1], cc[2], cc[3]);
    }
}

// ---------- gelu -> Wout GEMM -> GLU (per eval, 32 l per block) ----------
__global__ __launch_bounds__(256) void k_gemmglu(int layer, const float* __restrict__ bout){
    __shared__ __align__(16) float ygs[256*32];
    int e = blockIdx.x >> 11;
    int rem = blockIdx.x & 2047;
    int b = rem >> 7;
    int l0 = (rem & 127) << 5;
    int tid = threadIdx.x;
    for (int i = tid; i < 8192; i += 256){
        int hp = i >> 5, lt = i & 31;
        float v = g_conv[e*BHLc + (b*Hc + hp)*Lc + l0 + lt];
        ygs[i] = 0.5f * v * (1.0f + erff(v * 0.70710678f));
    }
    __syncthreads();
    int h = tid;
    u64 A[16], G[16];
    #pragma unroll
    for (int p = 0; p < 16; ++p){ A[p] = 0ull; G[p] = 0ull; }
    const float* w = g_woutT + (layer*2 + (e & 1))*131072;
    for (int hp = 0; hp < 256; ++hp){
        u64 wa = pack2(w[hp*512 + h]);
        u64 wg = pack2(w[hp*512 + 256 + h]);
        const ulonglong2* yp = (const ulonglong2*)&ygs[hp*32];
        #pragma unroll
        for (int j = 0; j < 8; ++j){
            ulonglong2 yv = yp[j];
            A[2*j]   = fma2(wa, yv.x, A[2*j]);
            G[2*j]   = fma2(wg, yv.x, G[2*j]);
            A[2*j+1] = fma2(wa, yv.y, A[2*j+1]);
            G[2*j+1] = fma2(wg, yv.y, G[2*j+1]);
        }
    }
    int lj = layer*2 + (e & 1);
    float ba = bout[lj*512 + h];
    float bg = bout[lj*512 + 256 + h];
    float res[32];
    #pragma unroll
    for (int p = 0; p < 16; ++p){
        float2 a = upk(A[p]), gg = upk(G[p]);
        res[2*p]   = (a.x + ba) / (1.0f + expf(-(gg.x + bg)));
        res[2*p+1] = (a.y + ba) / (1.0f + expf(-(gg.y + bg)));
    }
    float4* op = (float4*)&g_conv[e*BHLc + (b*Hc + h)*Lc + l0];
    #pragma unroll
    for (int j = 0; j < 8; ++j)
        op[j] = make_float4(res[4*j], res[4*j+1], res[4*j+2], res[4*j+3]);
}

// ---------- combine: residual + LayerNorm over H ----------
__global__ __launch_bounds__(256) void k_combine(int layer, const float* __restrict__ gam,
                                                 const float* __restrict__ bet){
    __shared__ float s0[256*9];
    __shared__ float s1[256*9];
    __shared__ float red[4][8][8];
    int b = blockIdx.x >> 9;
    int l0 = (blockIdx.x & 511) << 3;
    int tid = threadIdx.x;
    for (int i = tid; i < 2048; i += 256){
        int h = i >> 3, t = i & 7;
        int idx = (b*Hc + h)*Lc + l0 + t;
        s0[h*9 + t] = g_xr[idx] + g_conv[idx] - g_conv[BHLc + idx];
        s1[h*9 + t] = g_xi[idx] + g_conv[2*BHLc + idx] + g_conv[3*BHLc + idx];
    }
    __syncthreads();
    int warp = tid >> 5, lane = tid & 31;
    float vr[8], vi[8];
    #pragma unroll
    for (int t = 0; t < 8; ++t){ vr[t] = s0[tid*9 + t]; vi[t] = s1[tid*9 + t]; }
    #pragma unroll
    for (int t = 0; t < 8; ++t){
        float a = vr[t], a2 = vr[t]*vr[t], c = vi[t], c2 = vi[t]*vi[t];
        #pragma unroll
        for (int o = 16; o; o >>= 1){
            a  += __shfl_xor_sync(0xffffffffu, a, o);
            a2 += __shfl_xor_sync(0xffffffffu, a2, o);
            c  += __shfl_xor_sync(0xffffffffu, c, o);
            c2 += __shfl_xor_sync(0xffffffffu, c2, o);
        }
        if (lane == 0){ red[0][t][warp] = a; red[1][t][warp] = a2; red[2][t][warp] = c; red[3][t][warp] = c2; }
    }
    __syncthreads();
    float gr = gam[(layer*2)*256 + tid],     br = bet[(layer*2)*256 + tid];
    float gi = gam[(layer*2+1)*256 + tid],   bi = bet[(layer*2+1)*256 + tid];
    float outr[8], outi[8];
    #pragma unroll
    for (int t = 0; t < 8; ++t){
        float sR = 0, qR = 0, sI = 0, qI = 0;
        #pragma unroll
        for (int w = 0; w < 8; ++w){ sR += red[0][t][w]; qR += red[1][t][w]; sI += red[2][t][w]; qI += red[3][t][w]; }
        float mR = sR*(1.0f/256), vR = qR*(1.0f/256) - mR*mR;
        float mI = sI*(1.0f/256), vI = qI*(1.0f/256) - mI*mI;
        float rR = rsqrtf(vR + 1e-5f), rI = rsqrtf(vI + 1e-5f);
        outr[t] = (vr[t] - mR)*rR*gr + br;
        outi[t] = (vi[t] - mI)*rI*gi + bi;
    }
    int base = (b*Hc + tid)*Lc + l0;
    ((float4*)&g_xr[base])[0] = make_float4(outr[0], outr[1], outr[2], outr[3]);
    ((float4*)&g_xr[base])[1] = make_float4(outr[4], outr[5], outr[6], outr[7]);
    ((float4*)&g_xi[base])[0] = make_float4(outi[0], outi[1], outi[2], outi[3]);
    ((float4*)&g_xi[base])[1] = make_float4(outi[4], outi[5], outi[6], outi[7]);
}

// ---------- decoder: (B,H,L) -> out (B,L,257,2) ----------
__global__ __launch_bounds__(256) void k_decoder(const float* __restrict__ br,
                                                 const float* __restrict__ bi,
                                                 float* __restrict__ out){
    __shared__ __align__(16) float xsr[256*16];
    __shared__ __align__(16) float xsi[256*16];
    int b = blockIdx.x >> 8;
    int l0 = (blockIdx.x & 255) << 4;
    int tid = threadIdx.x;
    for (int i = tid; i < 4096; i += 256){
        int h = i >> 4, t = i & 15;
        int idx = (b*Hc + h)*Lc + l0 + t;
        xsr[i] = g_xr[idx];
        xsi[i] = g_xi[idx];
    }
    __syncthreads();
    for (int o = tid; o < DOUTc; o += 256){
        u64 pr[8], pi[8];
        #pragma unroll
        for (int p = 0; p < 8; ++p){ pr[p] = 0ull; pi[p] = 0ull; }
        for (int h = 0; h < 256; ++h){
            u64 wr2 = pack2(g_decT[0][h*DOUTc + o]);
            float wif = g_decT[1][h*DOUTc + o];
            u64 wi2 = pack2(wif), nwi2 = pack2(-wif);
            const ulonglong2* xr4 = (const ulonglong2*)&xsr[h*16];
            const ulonglong2* xi4 = (const ulonglong2*)&xsi[h*16];
            #pragma unroll
            for (int j = 0; j < 4; ++j){
                ulonglong2 xr = xr4[j], xi = xi4[j];
                pr[2*j]   = fma2(wr2, xr.x, pr[2*j]);   pr[2*j]   = fma2(nwi2, xi.x, pr[2*j]);
                pi[2*j]   = fma2(wi2, xr.x, pi[2*j]);   pi[2*j]   = fma2(wr2,  xi.x, pi[2*j]);
                pr[2*j+1] = fma2(wr2, xr.y, pr[2*j+1]); pr[2*j+1] = fma2(nwi2, xi.y, pr[2*j+1]);
                pi[2*j+1] = fma2(wi2, xr.y, pi[2*j+1]); pi[2*j+1] = fma2(wr2,  xi.y, pi[2*j+1]);
            }
        }
        float brv = br[o], biv = bi[o];
        #pragma unroll
        for (int p = 0; p < 8; ++p){
            float2 a = upk(pr[p]), c = upk(pi[p]);
            long long t0 = (long long)(b*Lc + l0 + 2*p)*DOUTc + o;
            long long t1 = (long long)(b*Lc + l0 + 2*p + 1)*DOUTc + o;
            ((float2*)out)[t0] = make_float2(a.x + brv, c.x + biv);
            ((float2*)out)[t1] = make_float2(a.y + brv, c.y + biv);
        }
    }
}

extern "C" void kernel_launch(void* const* d_in, const int* in_sizes, int n_in,
                              void* d_out, int out_size){
    const float* x    = (const float*)d_in[0];
    const float* eWr  = (const float*)d_in[1];
    const float* eWi  = (const float*)d_in[2];
    const float* ebr  = (const float*)d_in[3];
    const float* ebi  = (const float*)d_in[4];
    const float* ldt  = (const float*)d_in[5];
    const float* lAr  = (const float*)d_in[6];
    const float* Aim  = (const float*)d_in[7];
    const float* C2   = (const float*)d_in[8];
    const float* s4D  = (const float*)d_in[9];
    const float* Wout = (const float*)d_in[10];
    const float* bout = (const float*)d_in[11];
    const float* gam  = (const float*)d_in[12];
    const float* bet  = (const float*)d_in[13];
    const float* dWr  = (const float*)d_in[14];
    const float* dWi  = (const float*)d_in[15];
    const float* dbr  = (const float*)d_in[16];
    const float* dbi  = (const float*)d_in[17];
    float* out = (float*)d_out;

    k_prep_enc<<<64, 256>>>(eWr, eWi);
    k_prep_dec<<<64, 256>>>(dWr, dWi);
    k_prep_wout<<<512, 256>>>(Wout);
    k_coef<<<256, 256>>>(ldt, lAr, Aim, C2);
    k_encoder<<<4096, 256>>>(x, ebr, ebi);
    for (int l = 0; l < NLc; ++l){
        k_scan<<<512, 128>>>(l, s4D);
        k_gemmglu<<<8192, 256>>>(l, bout);
        k_combine<<<8192, 256>>>(l, gam, bet);
    }
    k_decoder<<<4096, 256>>>(dbr, dbi, out);
}

// round 4
// speedup vs baseline: 1.0009x; 1.0009x over previous
#include <cuda_runtime.h>
#include <math.h>

#define Bc 16
#define Lc 4096
#define Hc 256
#define Nc 32
#define DINc 257
#define DOUTc 257
#define NLc 4
#define BHLc (Bc*Hc*Lc)

__device__ float  g_xr[BHLc];
__device__ float  g_xi[BHLc];
__device__ float  g_conv[4*BHLc];
__device__ float  g_encT[2][DINc*Hc];
__device__ float  g_decT[2][Hc*DOUTc];
__device__ float  g_woutT[8*131072];
__device__ float4 g_coef[NLc*2*Hc*Nc];

typedef unsigned long long u64;

__device__ __forceinline__ u64 pack2(float v){ u64 r; asm("mov.b64 %0, {%1, %1};" : "=l"(r) : "f"(v)); return r; }
__device__ __forceinline__ u64 pk(float a, float b){ u64 r; asm("mov.b64 %0, {%1, %2};" : "=l"(r) : "f"(a), "f"(b)); return r; }
__device__ __forceinline__ u64 fma2(u64 a, u64 b, u64 c){ u64 d; asm("fma.rn.f32x2 %0, %1, %2, %3;" : "=l"(d) : "l"(a), "l"(b), "l"(c)); return d; }
__device__ __forceinline__ u64 mul2(u64 a, u64 b){ u64 d; asm("mul.rn.f32x2 %0, %1, %2;" : "=l"(d) : "l"(a), "l"(b)); return d; }
__device__ __forceinline__ float2 upk(u64 v){ float2 r; asm("mov.b64 {%0, %1}, %2;" : "=f"(r.x), "=f"(r.y) : "l"(v)); return r; }

// ---------- prep ----------
__global__ void k_prep_enc(const float* __restrict__ Wr, const float* __restrict__ Wi){
    for (int i = blockIdx.x*blockDim.x + threadIdx.x; i < DINc*Hc; i += gridDim.x*blockDim.x){
        int d = i >> 8, h = i & 255;
        g_encT[0][i] = Wr[h*DINc + d];
        g_encT[1][i] = Wi[h*DINc + d];
    }
}
__global__ void k_prep_dec(const float* __restrict__ Wr, const float* __restrict__ Wi){
    for (int i = blockIdx.x*blockDim.x + threadIdx.x; i < Hc*DOUTc; i += gridDim.x*blockDim.x){
        int h = i / DOUTc, o = i % DOUTc;
        g_decT[0][i] = Wr[o*Hc + h];
        g_decT[1][i] = Wi[o*Hc + h];
    }
}
__global__ void k_prep_wout(const float* __restrict__ W){
    for (int i = blockIdx.x*blockDim.x + threadIdx.x; i < 8*131072; i += gridDim.x*blockDim.x){
        int lj = i >> 17, r = i & 131071;
        int hp = r >> 9, o = r & 511;
        g_woutT[i] = W[lj*131072 + o*256 + hp];
    }
}
__global__ void k_coef(const float* __restrict__ log_dt, const float* __restrict__ logAr,
                       const float* __restrict__ Aim, const float* __restrict__ C2){
    int t = blockIdx.x*blockDim.x + threadIdx.x;
    if (t >= NLc*2*Hc*Nc) return;
    int n = t & 31, h = (t >> 5) & 255, lj = t >> 13;
    double dt = exp((double)log_dt[lj*256 + h]);
    int idx = (lj*256 + h)*32 + n;
    double Ar = -exp((double)logAr[idx]);
    double Ai = (double)Aim[idx];
    double dAr = dt*Ar, dAi = dt*Ai;
    double er = exp(dAr);
    double wr = er*cos(dAi), wi = er*sin(dAi);
    double den = Ar*Ar + Ai*Ai;
    double nr = wr - 1.0, ni = wi;
    double Fr = (nr*Ar + ni*Ai)/den;
    double Fi = (ni*Ar - nr*Ai)/den;
    double Cr = (double)C2[idx*2], Ci = (double)C2[idx*2+1];
    g_coef[idx] = make_float4((float)wr, (float)wi,
                              (float)( 2.0*(Cr*Fr - Ci*Fi)),
                              (float)(-2.0*(Cr*Fi + Ci*Fr)));
}

// ---------- encoder: (B,L,257,2) -> g_xr/g_xi (B,H,L) ----------
__global__ __launch_bounds__(256) void k_encoder(const float* __restrict__ x,
                                                 const float* __restrict__ br,
                                                 const float* __restrict__ bi){
    __shared__ __align__(16) float xsr[DINc*16];
    __shared__ __align__(16) float xsi[DINc*16];
    int b = blockIdx.x >> 8;
    int l0 = (blockIdx.x & 255) << 4;
    int tid = threadIdx.x;
    const float* xb = x + ((long long)(b*Lc + l0))*DINc*2;
    for (int i = tid; i < 16*DINc*2; i += 256){
        int t = i / (DINc*2), dd = i % (DINc*2);
        float v = xb[i];
        if (dd & 1) xsi[(dd>>1)*16 + t] = v; else xsr[(dd>>1)*16 + t] = v;
    }
    __syncthreads();
    int h = tid;
    u64 yr[8], yi[8];
    #pragma unroll
    for (int p = 0; p < 8; ++p){ yr[p] = 0ull; yi[p] = 0ull; }
    for (int d = 0; d < DINc; ++d){
        u64 wr2 = pack2(g_encT[0][d*256 + h]);
        float wif = g_encT[1][d*256 + h];
        u64 wi2 = pack2(wif), nwi2 = pack2(-wif);
        const ulonglong2* xr4 = (const ulonglong2*)&xsr[d*16];
        const ulonglong2* xi4 = (const ulonglong2*)&xsi[d*16];
        #pragma unroll
        for (int j = 0; j < 4; ++j){
            ulonglong2 xr = xr4[j], xi = xi4[j];
            yr[2*j]   = fma2(wr2, xr.x, yr[2*j]);   yr[2*j]   = fma2(nwi2, xi.x, yr[2*j]);
            yi[2*j]   = fma2(wi2, xr.x, yi[2*j]);   yi[2*j]   = fma2(wr2,  xi.x, yi[2*j]);
            yr[2*j+1] = fma2(wr2, xr.y, yr[2*j+1]); yr[2*j+1] = fma2(nwi2, xi.y, yr[2*j+1]);
            yi[2*j+1] = fma2(wi2, xr.y, yi[2*j+1]); yi[2*j+1] = fma2(wr2,  xi.y, yi[2*j+1]);
        }
    }
    float brv = br[h], biv = bi[h];
    float2* pr = (float2*)&g_xr[(b*Hc + h)*Lc + l0];
    float2* pi = (float2*)&g_xi[(b*Hc + h)*Lc + l0];
    #pragma unroll
    for (int p = 0; p < 8; ++p){
        float2 a = upk(yr[p]), c = upk(yi[p]);
        pr[p] = make_float2(a.x + brv, a.y + brv);
        pi[p] = make_float2(c.x + biv, c.y + biv);
    }
}

// ---------- S4D scan: 4 evals, 4 threads/(b,h), 4 packed mode-pairs/thread ----------
__global__ __launch_bounds__(128) void k_scan(int layer, const float* __restrict__ s4D){
    int e = blockIdx.x >> 7;
    int bhb = blockIdx.x & 127;
    int tid = threadIdx.x;
    int g = tid >> 2, q = tid & 3;
    int bh = bhb*32 + g;
    int h = bh & 255;
    int jb = e & 1;
    const float* u = ((e == 0 || e == 3) ? g_xr : g_xi) + bh*Lc;
    float* outp = g_conv + e*BHLc + bh*Lc;

    u64 wr2[4], wi2[4], nwi2[4], kr2[4], ki2[4], sr2[4], si2[4];
    int cbase = ((layer*2 + jb)*256 + h)*32 + q*8;
    #pragma unroll
    for (int m = 0; m < 4; ++m){
        float4 c0 = g_coef[cbase + 2*m];
        float4 c1 = g_coef[cbase + 2*m + 1];
        wr2[m] = pk(c0.x, c1.x);
        wi2[m] = pk(c0.y, c1.y);
        nwi2[m] = pk(-c0.y, -c1.y);
        kr2[m] = pk(c0.z, c1.z);
        ki2[m] = pk(c0.w, c1.w);
        sr2[m] = 0ull; si2[m] = 0ull;
    }
    float Dv = s4D[(layer*2 + jb)*256 + h];

    for (int l = 0; l < Lc; l += 4){
        float4 uv = *(const float4*)(u + l);
        float us[4] = {uv.x, uv.y, uv.z, uv.w};
        float cc[4];
        #pragma unroll
        for (int s = 0; s < 4; ++s){
            u64 u2 = pack2(us[s]), c2 = 0ull;
            #pragma unroll
            for (int m = 0; m < 4; ++m){
                u64 t0 = fma2(wr2[m], sr2[m], u2);
                t0 = fma2(nwi2[m], si2[m], t0);
                u64 t1 = mul2(wr2[m], si2[m]);
                t1 = fma2(wi2[m], sr2[m], t1);
                sr2[m] = t0; si2[m] = t1;
                c2 = fma2(kr2[m], t0, c2);
                c2 = fma2(ki2[m], t1, c2);
            }
            float2 cf = upk(c2);
            float c = cf.x + cf.y;
            c += __shfl_xor_sync(0xffffffffu, c, 1);
            c += __shfl_xor_sync(0xffffffffu, c, 2);
            cc[s] = fmaf(Dv, us[s], c);
        }
        if (q == 0) *(float4*)(outp + l) = make_float4(cc[0], cc[1], cc[2], cc[3]);
    }
}

// ---------- gelu -> Wout GEMM -> GLU (per eval, 32 l per block) ----------
__global__ __launch_bounds__(256) void k_gemmglu(int layer, const float* __restrict__ bout){
    __shared__ __align__(16) float ygs[256*32];
    int e = blockIdx.x >> 11;
    int rem = blockIdx.x & 2047;
    int b = rem >> 7;
    int l0 = (rem & 127) << 5;
    int tid = threadIdx.x;
    for (int i = tid; i < 8192; i += 256){
        int hp = i >> 5, lt = i & 31;
        float v = g_conv[e*BHLc + (b*Hc + hp)*Lc + l0 + lt];
        ygs[i] = 0.5f * v * (1.0f + erff(v * 0.70710678f));
    }
    __syncthreads();
    int h = tid;
    u64 A[16], G[16];
    #pragma unroll
    for (int p = 0; p < 16; ++p){ A[p] = 0ull; G[p] = 0ull; }
    const float* w = g_woutT + (layer*2 + (e & 1))*131072;
    for (int hp = 0; hp < 256; ++hp){
        u64 wa = pack2(w[hp*512 + h]);
        u64 wg = pack2(w[hp*512 + 256 + h]);
        const ulonglong2* yp = (const ulonglong2*)&ygs[hp*32];
        #pragma unroll
        for (int j = 0; j < 8; ++j){
            ulonglong2 yv = yp[j];
            A[2*j]   = fma2(wa, yv.x, A[2*j]);
            G[2*j]   = fma2(wg, yv.x, G[2*j]);
            A[2*j+1] = fma2(wa, yv.y, A[2*j+1]);
            G[2*j+1] = fma2(wg, yv.y, G[2*j+1]);
        }
    }
    int lj = layer*2 + (e & 1);
    float ba = bout[lj*512 + h];
    float bg = bout[lj*512 + 256 + h];
    float res[32];
    #pragma unroll
    for (int p = 0; p < 16; ++p){
        float2 a = upk(A[p]), gg = upk(G[p]);
        res[2*p]   = (a.x + ba) / (1.0f + expf(-(gg.x + bg)));
        res[2*p+1] = (a.y + ba) / (1.0f + expf(-(gg.y + bg)));
    }
    float4* op = (float4*)&g_conv[e*BHLc + (b*Hc + h)*Lc + l0];
    #pragma unroll
    for (int j = 0; j < 8; ++j)
        op[j] = make_float4(res[4*j], res[4*j+1], res[4*j+2], res[4*j+3]);
}

// ---------- combine: residual + LayerNorm over H ----------
__global__ __launch_bounds__(256) void k_combine(int layer, const float* __restrict__ gam,
                                                 const float* __restrict__ bet){
    __shared__ float s0[256*9];
    __shared__ float s1[256*9];
    __shared__ float red[4][8][8];
    int b = blockIdx.x >> 9;
    int l0 = (blockIdx.x & 511) << 3;
    int tid = threadIdx.x;
    for (int i = tid; i < 2048; i += 256){
        int h = i >> 3, t = i & 7;
        int idx = (b*Hc + h)*Lc + l0 + t;
        s0[h*9 + t] = g_xr[idx] + g_conv[idx] - g_conv[BHLc + idx];
        s1[h*9 + t] = g_xi[idx] + g_conv[2*BHLc + idx] + g_conv[3*BHLc + idx];
    }
    __syncthreads();
    int warp = tid >> 5, lane = tid & 31;
    float vr[8], vi[8];
    #pragma unroll
    for (int t = 0; t < 8; ++t){ vr[t] = s0[tid*9 + t]; vi[t] = s1[tid*9 + t]; }
    #pragma unroll
    for (int t = 0; t < 8; ++t){
        float a = vr[t], a2 = vr[t]*vr[t], c = vi[t], c2 = vi[t]*vi[t];
        #pragma unroll
        for (int o = 16; o; o >>= 1){
            a  += __shfl_xor_sync(0xffffffffu, a, o);
            a2 += __shfl_xor_sync(0xffffffffu, a2, o);
            c  += __shfl_xor_sync(0xffffffffu, c, o);
            c2 += __shfl_xor_sync(0xffffffffu, c2, o);
        }
        if (lane == 0){ red[0][t][warp] = a; red[1][t][warp] = a2; red[2][t][warp] = c; red[3][t][warp] = c2; }
    }
    __syncthreads();
    float gr = gam[(layer*2)*256 + tid],     br = bet[(layer*2)*256 + tid];
    float gi = gam[(layer*2+1)*256 + tid],   bi = bet[(layer*2+1)*256 + tid];
    float outr[8], outi[8];
    #pragma unroll
    for (int t = 0; t < 8; ++t){
        float sR = 0, qR = 0, sI = 0, qI = 0;
        #pragma unroll
        for (int w = 0; w < 8; ++w){ sR += red[0][t][w]; qR += red[1][t][w]; sI += red[2][t][w]; qI += red[3][t][w]; }
        float mR = sR*(1.0f/256), vR = qR*(1.0f/256) - mR*mR;
        float mI = sI*(1.0f/256), vI = qI*(1.0f/256) - mI*mI;
        float rR = rsqrtf(vR + 1e-5f), rI = rsqrtf(vI + 1e-5f);
        outr[t] = (vr[t] - mR)*rR*gr + br;
        outi[t] = (vi[t] - mI)*rI*gi + bi;
    }
    int base = (b*Hc + tid)*Lc + l0;
    ((float4*)&g_xr[base])[0] = make_float4(outr[0], outr[1], outr[2], outr[3]);
    ((float4*)&g_xr[base])[1] = make_float4(outr[4], outr[5], outr[6], outr[7]);
    ((float4*)&g_xi[base])[0] = make_float4(outi[0], outi[1], outi[2], outi[3]);
    ((float4*)&g_xi[base])[1] = make_float4(outi[4], outi[5], outi[6], outi[7]);
}

// ---------- decoder: (B,H,L) -> out (B,L,257,2) ----------
__global__ __launch_bounds__(256) void k_decoder(const float* __restrict__ br,
                                                 const float* __restrict__ bi,
                                                 float* __restrict__ out){
    __shared__ __align__(16) float xsr[256*16];
    __shared__ __align__(16) float xsi[256*16];
    int b = blockIdx.x >> 8;
    int l0 = (blockIdx.x & 255) << 4;
    int tid = threadIdx.x;
    for (int i = tid; i < 4096; i += 256){
        int h = i >> 4, t = i & 15;
        int idx = (b*Hc + h)*Lc + l0 + t;
        xsr[i] = g_xr[idx];
        xsi[i] = g_xi[idx];
    }
    __syncthreads();
    for (int o = tid; o < DOUTc; o += 256){
        u64 pr[8], pi[8];
        #pragma unroll
        for (int p = 0; p < 8; ++p){ pr[p] = 0ull; pi[p] = 0ull; }
        for (int h = 0; h < 256; ++h){
            u64 wr2 = pack2(g_decT[0][h*DOUTc + o]);
            float wif = g_decT[1][h*DOUTc + o];
            u64 wi2 = pack2(wif), nwi2 = pack2(-wif);
            const ulonglong2* xr4 = (const ulonglong2*)&xsr[h*16];
            const ulonglong2* xi4 = (const ulonglong2*)&xsi[h*16];
            #pragma unroll
            for (int j = 0; j < 4; ++j){
                ulonglong2 xr = xr4[j], xi = xi4[j];
                pr[2*j]   = fma2(wr2, xr.x, pr[2*j]);   pr[2*j]   = fma2(nwi2, xi.x, pr[2*j]);
                pi[2*j]   = fma2(wi2, xr.x, pi[2*j]);   pi[2*j]   = fma2(wr2,  xi.x, pi[2*j]);
                pr[2*j+1] = fma2(wr2, xr.y, pr[2*j+1]); pr[2*j+1] = fma2(nwi2, xi.y, pr[2*j+1]);
                pi[2*j+1] = fma2(wi2, xr.y, pi[2*j+1]); pi[2*j+1] = fma2(wr2,  xi.y, pi[2*j+1]);
            }
        }
        float brv = br[o], biv = bi[o];
        #pragma unroll
        for (int p = 0; p < 8; ++p){
            float2 a = upk(pr[p]), c = upk(pi[p]);
            long long t0 = (long long)(b*Lc + l0 + 2*p)*DOUTc + o;
            long long t1 = (long long)(b*Lc + l0 + 2*p + 1)*DOUTc + o;
            ((float2*)out)[t0] = make_float2(a.x + brv, c.x + biv);
            ((float2*)out)[t1] = make_float2(a.y + brv, c.y + biv);
        }
    }
}

extern "C" void kernel_launch(void* const* d_in, const int* in_sizes, int n_in,
                              void* d_out, int out_size){
    const float* x    = (const float*)d_in[0];
    const float* eWr  = (const float*)d_in[1];
    const float* eWi  = (const float*)d_in[2];
    const float* ebr  = (const float*)d_in[3];
    const float* ebi  = (const float*)d_in[4];
    const float* ldt  = (const float*)d_in[5];
    const float* lAr  = (const float*)d_in[6];
    const float* Aim  = (const float*)d_in[7];
    const float* C2   = (const float*)d_in[8];
    const float* s4D  = (const float*)d_in[9];
    const float* Wout = (const float*)d_in[10];
    const float* bout = (const float*)d_in[11];
    const float* gam  = (const float*)d_in[12];
    const float* bet  = (const float*)d_in[13];
    const float* dWr  = (const float*)d_in[14];
    const float* dWi  = (const float*)d_in[15];
    const float* dbr  = (const float*)d_in[16];
    const float* dbi  = (const float*)d_in[17];
    float* out = (float*)d_out;

    k_prep_enc<<<64, 256>>>(eWr, eWi);
    k_prep_dec<<<64, 256>>>(dWr, dWi);
    k_prep_wout<<<512, 256>>>(Wout);
    k_coef<<<256, 256>>>(ldt, lAr, Aim, C2);
    k_encoder<<<4096, 256>>>(x, ebr, ebi);
    for (int l = 0; l < NLc; ++l){
        k_scan<<<512, 128>>>(l, s4D);
        k_gemmglu<<<8192, 256>>>(l, bout);
        k_combine<<<8192, 256>>>(l, gam, bet);
    }
    k_decoder<<<4096, 256>>>(dbr, dbi, out);
}

// round 6
// speedup vs baseline: 1.0054x; 1.0045x over previous
#include <cuda_runtime.h>
#include <cuda_bf16.h>
#include <math.h>

#define Bc 16
#define Lc 4096
#define Hc 256
#define DINc 257
#define DOUTc 257
#define NLc 4
#define BHLc (Bc*Hc*Lc)

__device__ float  g_xr[BHLc];
__device__ float  g_xi[BHLc];
__device__ float  g_conv[4*BHLc];
__device__ unsigned short g_cbh[4*BHLc];
__device__ unsigned short g_cbl[4*BHLc];
__device__ float  g_encT[2][DINc*Hc];
__device__ float  g_decT[2][Hc*DOUTc];
__device__ float4 g_coef[NLc*2*Hc*32];

typedef unsigned long long u64;
typedef unsigned int u32;

__device__ __forceinline__ u64 pack2(float v){ u64 r; asm("mov.b64 %0, {%1, %1};" : "=l"(r) : "f"(v)); return r; }
__device__ __forceinline__ u64 pk(float a, float b){ u64 r; asm("mov.b64 %0, {%1, %2};" : "=l"(r) : "f"(a), "f"(b)); return r; }
__device__ __forceinline__ u64 fma2(u64 a, u64 b, u64 c){ u64 d; asm("fma.rn.f32x2 %0, %1, %2, %3;" : "=l"(d) : "l"(a), "l"(b), "l"(c)); return d; }
__device__ __forceinline__ u64 mul2(u64 a, u64 b){ u64 d; asm("mul.rn.f32x2 %0, %1, %2;" : "=l"(d) : "l"(a), "l"(b)); return d; }
__device__ __forceinline__ float2 upk(u64 v){ float2 r; asm("mov.b64 {%0, %1}, %2;" : "=f"(r.x), "=f"(r.y) : "l"(v)); return r; }
__device__ __forceinline__ u32 smem_u32(const void* p){ u32 a; asm("{ .reg .u64 t; cvta.to.shared.u64 t, %1; cvt.u32.u64 %0, t; }" : "=r"(a) : "l"(p)); return a; }
__device__ __forceinline__ void bfsplit(float v, unsigned short& h, unsigned short& l){
    __nv_bfloat16 hb = __float2bfloat16(v);
    float r = v - __bfloat162float(hb);
    __nv_bfloat16 lb = __float2bfloat16(r);
    h = *(unsigned short*)&hb; l = *(unsigned short*)&lb;
}
__device__ __forceinline__ void ldsm4(u32* r, u32 a){
    asm volatile("ldmatrix.sync.aligned.m8n8.x4.shared.b16 {%0,%1,%2,%3}, [%4];"
        : "=r"(r[0]), "=r"(r[1]), "=r"(r[2]), "=r"(r[3]) : "r"(a));
}
__device__ __forceinline__ void ldsm4t(u32* r, u32 a){
    asm volatile("ldmatrix.sync.aligned.m8n8.x4.trans.shared.b16 {%0,%1,%2,%3}, [%4];"
        : "=r"(r[0]), "=r"(r[1]), "=r"(r[2]), "=r"(r[3]) : "r"(a));
}
__device__ __forceinline__ void mmabf(float* d, const u32* a, const u32* b){
    asm volatile("mma.sync.aligned.m16n8k16.row.col.f32.bf16.bf16.f32 "
        "{%0,%1,%2,%3},{%4,%5,%6,%7},{%8,%9},{%0,%1,%2,%3};"
        : "+f"(d[0]), "+f"(d[1]), "+f"(d[2]), "+f"(d[3])
        : "r"(a[0]), "r"(a[1]), "r"(a[2]), "r"(a[3]), "r"(b[0]), "r"(b[1]));
}

// ---------- prep ----------
__global__ void k_prep(const float* __restrict__ eWr, const float* __restrict__ eWi,
                       const float* __restrict__ dWr, const float* __restrict__ dWi){
    for (int i = blockIdx.x*blockDim.x + threadIdx.x; i < DINc*Hc; i += gridDim.x*blockDim.x){
        int d = i >> 8, h = i & 255;
        g_encT[0][i] = eWr[h*DINc + d];
        g_encT[1][i] = eWi[h*DINc + d];
        int h2 = i / DOUTc, o = i % DOUTc;
        if (h2 < Hc){ g_decT[0][i] = dWr[o*Hc + h2]; g_decT[1][i] = dWi[o*Hc + h2]; }
    }
}
__global__ void k_coef(const float* __restrict__ log_dt, const float* __restrict__ logAr,
                       const float* __restrict__ Aim, const float* __restrict__ C2){
    int t = blockIdx.x*blockDim.x + threadIdx.x;
    if (t >= NLc*2*Hc*32) return;
    int h = (t >> 5) & 255, lj = t >> 13;
    double dt = exp((double)log_dt[lj*256 + h]);
    double Ar = -exp((double)logAr[t]);
    double Ai = (double)Aim[t];
    double er = exp(dt*Ar);
    double wr = er*cos(dt*Ai), wi = er*sin(dt*Ai);
    double den = Ar*Ar + Ai*Ai;
    double Fr = ((wr-1.0)*Ar + wi*Ai)/den;
    double Fi = (wi*Ar - (wr-1.0)*Ai)/den;
    double Cr = (double)C2[t*2], Ci = (double)C2[t*2+1];
    g_coef[t] = make_float4((float)wr, (float)wi, (float)(2.0*(Cr*Fr - Ci*Fi)), (float)(-2.0*(Cr*Fi + Ci*Fr)));
}

// ---------- encoder ----------
__global__ __launch_bounds__(256) void k_encoder(const float* __restrict__ x,
                                                 const float* __restrict__ br, const float* __restrict__ bi){
    __shared__ __align__(16) float xsr[DINc*16];
    __shared__ __align__(16) float xsi[DINc*16];
    int b = blockIdx.x >> 8, l0 = (blockIdx.x & 255) << 4, tid = threadIdx.x;
    const float* xb = x + ((long long)(b*Lc + l0))*DINc*2;
    for (int i = tid; i < 16*DINc*2; i += 256){
        int t = i / (DINc*2), dd = i % (DINc*2);
        float v = xb[i];
        if (dd & 1) xsi[(dd>>1)*16 + t] = v; else xsr[(dd>>1)*16 + t] = v;
    }
    __syncthreads();
    int h = tid;
    u64 yr[8], yi[8];
    #pragma unroll
    for (int p = 0; p < 8; ++p){ yr[p] = 0ull; yi[p] = 0ull; }
    for (int d = 0; d < DINc; ++d){
        u64 wr2 = pack2(g_encT[0][d*256 + h]);
        float wif = g_encT[1][d*256 + h];
        u64 wi2 = pack2(wif), nwi2 = pack2(-wif);
        const ulonglong2* xr4 = (const ulonglong2*)&xsr[d*16];
        const ulonglong2* xi4 = (const ulonglong2*)&xsi[d*16];
        #pragma unroll
        for (int j = 0; j < 4; ++j){
            ulonglong2 xr = xr4[j], xi = xi4[j];
            yr[2*j]   = fma2(wr2, xr.x, yr[2*j]);   yr[2*j]   = fma2(nwi2, xi.x, yr[2*j]);
            yi[2*j]   = fma2(wi2, xr.x, yi[2*j]);   yi[2*j]   = fma2(wr2,  xi.x, yi[2*j]);
            yr[2*j+1] = fma2(wr2, xr.y, yr[2*j+1]); yr[2*j+1] = fma2(nwi2, xi.y, yr[2*j+1]);
            yi[2*j+1] = fma2(wi2, xr.y, yi[2*j+1]); yi[2*j+1] = fma2(wr2,  xi.y, yi[2*j+1]);
        }
    }
    float brv = br[h], biv = bi[h];
    float2* pr = (float2*)&g_xr[(b*Hc + h)*Lc + l0];
    float2* pi = (float2*)&g_xi[(b*Hc + h)*Lc + l0];
    #pragma unroll
    for (int p = 0; p < 8; ++p){
        float2 a = upk(yr[p]), c = upk(yi[p]);
        pr[p] = make_float2(a.x + brv, a.y + brv);
        pi[p] = make_float2(c.x + biv, c.y + biv);
    }
}

// ---------- scan + fused gelu + bf16 split ----------
__global__ __launch_bounds__(128) void k_scan(int layer, const float* __restrict__ s4D){
    int e = blockIdx.x >> 7, bhb = blockIdx.x & 127, tid = threadIdx.x;
    int g = tid >> 2, q = tid & 3;
    int bh = bhb*32 + g, h = bh & 255, jb = e & 1;
    const float* u = ((e == 0 || e == 3) ? g_xr : g_xi) + bh*Lc;
    int cb = e*BHLc + bh*Lc;
    u64 wr2[4], wi2[4], nwi2[4], kr2[4], ki2[4], sr2[4], si2[4];
    int cbase = ((layer*2 + jb)*256 + h)*32 + q*8;
    #pragma unroll
    for (int m = 0; m < 4; ++m){
        float4 c0 = g_coef[cbase + 2*m];
        float4 c1 = g_coef[cbase + 2*m + 1];
        wr2[m] = pk(c0.x, c1.x); wi2[m] = pk(c0.y, c1.y); nwi2[m] = pk(-c0.y, -c1.y);
        kr2[m] = pk(c0.z, c1.z); ki2[m] = pk(c0.w, c1.w);
        sr2[m] = 0ull; si2[m] = 0ull;
    }
    float Dv = s4D[(layer*2 + jb)*256 + h];
    for (int l = 0; l < Lc; l += 4){
        float4 uv = *(const float4*)(u + l);
        float us[4] = {uv.x, uv.y, uv.z, uv.w};
        float cc[4];
        #pragma unroll
        for (int s = 0; s < 4; ++s){
            u64 u2 = pack2(us[s]), c2 = 0ull;
            #pragma unroll
            for (int m = 0; m < 4; ++m){
                u64 t0 = fma2(wr2[m], sr2[m], u2);
                t0 = fma2(nwi2[m], si2[m], t0);
                u64 t1 = mul2(wr2[m], si2[m]);
                t1 = fma2(wi2[m], sr2[m], t1);
                sr2[m] = t0; si2[m] = t1;
                c2 = fma2(kr2[m], t0, c2);
                c2 = fma2(ki2[m], t1, c2);
            }
            float2 cf = upk(c2);
            float c = cf.x + cf.y;
            c += __shfl_xor_sync(0xffffffffu, c, 1);
            c += __shfl_xor_sync(0xffffffffu, c, 2);
            cc[s] = fmaf(Dv, us[s], c);
        }
        if (q == 0){
            ushort4 hh, ll;
            float g0 = 0.5f*cc[0]*(1.0f + erff(cc[0]*0.70710678f));
            float g1 = 0.5f*cc[1]*(1.0f + erff(cc[1]*0.70710678f));
            float g2 = 0.5f*cc[2]*(1.0f + erff(cc[2]*0.70710678f));
            float g3 = 0.5f*cc[3]*(1.0f + erff(cc[3]*0.70710678f));
            bfsplit(g0, hh.x, ll.x); bfsplit(g1, hh.y, ll.y);
            bfsplit(g2, hh.z, ll.z); bfsplit(g3, hh.w, ll.w);
            *(ushort4*)&g_cbh[cb + l] = hh;
            *(ushort4*)&g_cbl[cb + l] = ll;
        }
    }
}

// ---------- HMMA GEMM + GLU ----------
// SMEM: A_hi[0,64K) A_lo[64K,128K) B_hi[128K,160K) B_lo[160K,192K); sbuf reuses B region
// A[m][k]: 128x256 bf16, off = (m*512+k*2) ^ ((m&7)<<4)
// B[k][n]: 256x64 bf16,  off = (k*128+n*2) ^ ((k&7)<<4)
__global__ __launch_bounds__(256) void k_gemm(int layer, const float* __restrict__ Wout,
                                              const float* __restrict__ bout){
    extern __shared__ __align__(1024) char sm[];
    u32 smb = smem_u32(sm);
    int tid = threadIdx.x, wid = tid >> 5, lane = tid & 31;
    int j = blockIdx.x >> 6, ob = (blockIdx.x >> 4) & 3, b = blockIdx.x & 15;
    int lj = layer*2 + j;
    const float* Ws = Wout + lj*131072;
    {
        int r = tid >> 1, c0 = (tid & 1)*128;
        int o = (r < 64) ? ob*64 + r : 256 + ob*64 + (r - 64);
        const float4* src = (const float4*)(Ws + o*256 + c0);
        u32 axr = (u32)(r & 7) << 4;
        for (int c4 = 0; c4 < 32; ++c4){
            float4 v = src[c4];
            int c = c0 + c4*4;
            u32 off = ((u32)(r*512 + c*2)) ^ axr;
            ushort4 hh, ll;
            bfsplit(v.x, hh.x, ll.x); bfsplit(v.y, hh.y, ll.y);
            bfsplit(v.z, hh.z, ll.z); bfsplit(v.w, hh.w, ll.w);
            *(ushort4*)(sm + off) = hh;
            *(ushort4*)(sm + 65536 + off) = ll;
        }
    }
    __syncthreads();
    int wm = wid >> 1, wn = wid & 1;
    int sel = lane >> 3, l7 = lane & 7;
    int ar0 = wm*32 + (sel & 1)*8 + l7;     // A frag row (mt adds 16)
    int akk = (sel >> 1)*8;                  // A frag k offset
    u32 axor = (u32)(ar0 & 7) << 4;
    int bkk = (sel & 1)*8 + l7;              // B frag k offset
    u32 bxor = (u32)l7 << 4;
    float* sbuf = (float*)(sm + 131072);
    int er_ = tid >> 2, cg_ = tid & 3;
    int o_ = ob*64 + er_;
    float ba_ = bout[lj*512 + o_], bg_ = bout[lj*512 + 256 + o_];
    for (int ti = 0; ti < 128; ++ti){
        int e = j + (ti >> 6)*2;
        int l0 = (ti & 63) << 6;
        {
            long long sidx = (long long)e*BHLc + ((long long)(b*256 + tid))*Lc + l0;
            const uint4* sh = (const uint4*)(g_cbh + sidx);
            const uint4* sl = (const uint4*)(g_cbl + sidx);
            u32 bx = (u32)(tid & 7) << 4;
            #pragma unroll
            for (int i = 0; i < 8; ++i){
                u32 off = ((u32)(tid*128 + i*16)) ^ bx;
                *(uint4*)(sm + 131072 + off) = sh[i];
                *(uint4*)(sm + 163840 + off) = sl[i];
            }
        }
        __syncthreads();
        float acc[2][4][4];
        #pragma unroll
        for (int mt = 0; mt < 2; ++mt)
            #pragma unroll
            for (int nt = 0; nt < 4; ++nt){ acc[mt][nt][0]=0.f; acc[mt][nt][1]=0.f; acc[mt][nt][2]=0.f; acc[mt][nt][3]=0.f; }
        #pragma unroll 4
        for (int ks = 0; ks < 16; ++ks){
            int k0 = ks*16;
            u32 ah[2][4], al[2][4], bh[4][2], bl[4][2];
            #pragma unroll
            for (int mt = 0; mt < 2; ++mt){
                u32 off = ((u32)((ar0 + mt*16)*512 + (akk + k0)*2)) ^ axor;
                ldsm4(ah[mt], smb + off);
                ldsm4(al[mt], smb + 65536 + off);
            }
            #pragma unroll
            for (int nb = 0; nb < 2; ++nb){
                int nn = wn*32 + nb*16 + (sel >> 1)*8;
                u32 off = ((u32)((bkk + k0)*128 + nn*2)) ^ bxor;
                u32 t[4];
                ldsm4t(t, smb + 131072 + off);
                bh[nb*2][0]=t[0]; bh[nb*2][1]=t[1]; bh[nb*2+1][0]=t[2]; bh[nb*2+1][1]=t[3];
                ldsm4t(t, smb + 163840 + off);
                bl[nb*2][0]=t[0]; bl[nb*2][1]=t[1]; bl[nb*2+1][0]=t[2]; bl[nb*2+1][1]=t[3];
            }
            #pragma unroll
            for (int mt = 0; mt < 2; ++mt)
                #pragma unroll
                for (int nt = 0; nt < 4; ++nt){
                    mmabf(acc[mt][nt], ah[mt], bh[nt]);
                    mmabf(acc[mt][nt], al[mt], bh[nt]);
                    mmabf(acc[mt][nt], ah[mt], bl[nt]);
                }
        }
        __syncthreads();
        {
            int rw = wm*32 + (lane >> 2);
            int cw = wn*32 + (lane & 3)*2;
            #pragma unroll
            for (int mt = 0; mt < 2; ++mt)
                #pragma unroll
                for (int nt = 0; nt < 4; ++nt){
                    int rr = rw + mt*16, cc = cw + nt*8;
                    sbuf[rr*65 + cc]       = acc[mt][nt][0];
                    sbuf[rr*65 + cc + 1]   = acc[mt][nt][1];
                    sbuf[(rr+8)*65 + cc]   = acc[mt][nt][2];
                    sbuf[(rr+8)*65 + cc+1] = acc[mt][nt][3];
                }
        }
        __syncthreads();
        {
            const float* pa = sbuf + er_*65 + cg_*16;
            const float* pg = sbuf + (64 + er_)*65 + cg_*16;
            float4* dst = (float4*)&g_conv[(long long)e*BHLc + (b*256 + o_)*Lc + l0 + cg_*16];
            #pragma unroll
            for (int qd = 0; qd < 4; ++qd){
                float4 ov;
                ov.x = (pa[qd*4+0] + ba_) / (1.0f + expf(-(pg[qd*4+0] + bg_)));
                ov.y = (pa[qd*4+1] + ba_) / (1.0f + expf(-(pg[qd*4+1] + bg_)));
                ov.z = (pa[qd*4+2] + ba_) / (1.0f + expf(-(pg[qd*4+2] + bg_)));
                ov.w = (pa[qd*4+3] + ba_) / (1.0f + expf(-(pg[qd*4+3] + bg_)));
                dst[qd] = ov;
            }
        }
        __syncthreads();
    }
}

// ---------- combine: residual + LayerNorm ----------
__global__ __launch_bounds__(256) void k_combine(int layer, const float* __restrict__ gam,
                                                 const float* __restrict__ bet){
    __shared__ float s0[256*9];
    __shared__ float s1[256*9];
    __shared__ float red[4][8][8];
    int b = blockIdx.x >> 9, l0 = (blockIdx.x & 511) << 3, tid = threadIdx.x;
    for (int i = tid; i < 2048; i += 256){
        int h = i >> 3, t = i & 7;
        int idx = (b*Hc + h)*Lc + l0 + t;
        s0[h*9 + t] = g_xr[idx] + g_conv[idx] - g_conv[BHLc + idx];
        s1[h*9 + t] = g_xi[idx] + g_conv[2*BHLc + idx] + g_conv[3*BHLc + idx];
    }
    __syncthreads();
    int warp = tid >> 5, lane = tid & 31;
    float vr[8], vi[8];
    #pragma unroll
    for (int t = 0; t < 8; ++t){ vr[t] = s0[tid*9 + t]; vi[t] = s1[tid*9 + t]; }
    #pragma unroll
    for (int t = 0; t < 8; ++t){
        float a = vr[t], a2 = vr[t]*vr[t], c = vi[t], c2 = vi[t]*vi[t];
        #pragma unroll
        for (int o = 16; o; o >>= 1){
            a  += __shfl_xor_sync(0xffffffffu, a, o);
            a2 += __shfl_xor_sync(0xffffffffu, a2, o);
            c  += __shfl_xor_sync(0xffffffffu, c, o);
            c2 += __shfl_xor_sync(0xffffffffu, c2, o);
        }
        if (lane == 0){ red[0][t][warp] = a; red[1][t][warp] = a2; red[2][t][warp] = c; red[3][t][warp] = c2; }
    }
    __syncthreads();
    float gr = gam[(layer*2)*256 + tid],   brr = bet[(layer*2)*256 + tid];
    float gi = gam[(layer*2+1)*256 + tid], bii = bet[(layer*2+1)*256 + tid];
    float outr[8], outi[8];
    #pragma unroll
    for (int t = 0; t < 8; ++t){
        float sR = 0, qR = 0, sI = 0, qI = 0;
        #pragma unroll
        for (int w = 0; w < 8; ++w){ sR += red[0][t][w]; qR += red[1][t][w]; sI += red[2][t][w]; qI += red[3][t][w]; }
        float mR = sR*(1.0f/256), vR = qR*(1.0f/256) - mR*mR;
        float mI = sI*(1.0f/256), vI = qI*(1.0f/256) - mI*mI;
        float rR = rsqrtf(vR + 1e-5f), rI = rsqrtf(vI + 1e-5f);
        outr[t] = (vr[t] - mR)*rR*gr + brr;
        outi[t] = (vi[t] - mI)*rI*gi + bii;
    }
    int base = (b*Hc + tid)*Lc + l0;
    ((float4*)&g_xr[base])[0] = make_float4(outr[0], outr[1], outr[2], outr[3]);
    ((float4*)&g_xr[base])[1] = make_float4(outr[4], outr[5], outr[6], outr[7]);
    ((float4*)&g_xi[base])[0] = make_float4(outi[0], outi[1], outi[2], outi[3]);
    ((float4*)&g_xi[base])[1] = make_float4(outi[4], outi[5], outi[6], outi[7]);
}

// ---------- decoder ----------
__global__ __launch_bounds__(256) void k_decoder(const float* __restrict__ br,
                                                 const float* __restrict__ bi, float* __restrict__ out){
    __shared__ __align__(16) float xsr[256*16];
    __shared__ __align__(16) float xsi[256*16];
    int b = blockIdx.x >> 8, l0 = (blockIdx.x & 255) << 4, tid = threadIdx.x;
    for (int i = tid; i < 4096; i += 256){
        int h = i >> 4, t = i & 15;
        int idx = (b*Hc + h)*Lc + l0 + t;
        xsr[i] = g_xr[idx]; xsi[i] = g_xi[idx];
    }
    __syncthreads();
    for (int o = tid; o < DOUTc; o += 256){
        u64 pr[8], pi[8];
        #pragma unroll
        for (int p = 0; p < 8; ++p){ pr[p] = 0ull; pi[p] = 0ull; }
        for (int h = 0; h < 256; ++h){
            u64 wr2 = pack2(g_decT[0][h*DOUTc + o]);
            float wif = g_decT[1][h*DOUTc + o];
            u64 wi2 = pack2(wif), nwi2 = pack2(-wif);
            const ulonglong2* xr4 = (const ulonglong2*)&xsr[h*16];
            const ulonglong2* xi4 = (const ulonglong2*)&xsi[h*16];
            #pragma unroll
            for (int jq = 0; jq < 4; ++jq){
                ulonglong2 xr = xr4[jq], xi = xi4[jq];
                pr[2*jq]   = fma2(wr2, xr.x, pr[2*jq]);   pr[2*jq]   = fma2(nwi2, xi.x, pr[2*jq]);
                pi[2*jq]   = fma2(wi2, xr.x, pi[2*jq]);   pi[2*jq]   = fma2(wr2,  xi.x, pi[2*jq]);
                pr[2*jq+1] = fma2(wr2, xr.y, pr[2*jq+1]); pr[2*jq+1] = fma2(nwi2, xi.y, pr[2*jq+1]);
                pi[2*jq+1] = fma2(wi2, xr.y, pi[2*jq+1]); pi[2*jq+1] = fma2(wr2,  xi.y, pi[2*jq+1]);
            }
        }
        float brv = br[o], biv = bi[o];
        #pragma unroll
        for (int p = 0; p < 8; ++p){
            float2 a = upk(pr[p]), c = upk(pi[p]);
            long long t0 = (long long)(b*Lc + l0 + 2*p)*DOUTc + o;
            ((float2*)out)[t0] = make_float2(a.x + brv, c.x + biv);
            ((float2*)out)[t0 + DOUTc] = make_float2(a.y + brv, c.y + biv);
        }
    }
}

extern "C" void kernel_launch(void* const* d_in, const int* in_sizes, int n_in,
                              void* d_out, int out_size){
    const float* x    = (const float*)d_in[0];
    const float* eWr  = (const float*)d_in[1];
    const float* eWi  = (const float*)d_in[2];
    const float* ebr  = (const float*)d_in[3];
    const float* ebi  = (const float*)d_in[4];
    const float* ldt  = (const float*)d_in[5];
    const float* lAr  = (const float*)d_in[6];
    const float* Aim  = (const float*)d_in[7];
    const float* C2   = (const float*)d_in[8];
    const float* s4D  = (const float*)d_in[9];
    const float* Wout = (const float*)d_in[10];
    const float* bout = (const float*)d_in[11];
    const float* gam  = (const float*)d_in[12];
    const float* bet  = (const float*)d_in[13];
    const float* dWr  = (const float*)d_in[14];
    const float* dWi  = (const float*)d_in[15];
    const float* dbr  = (const float*)d_in[16];
    const float* dbi  = (const float*)d_in[17];
    float* out = (float*)d_out;

    cudaFuncSetAttribute(k_gemm, cudaFuncAttributeMaxDynamicSharedMemorySize, 196608);
    k_prep<<<64, 256>>>(eWr, eWi, dWr, dWi);
    k_coef<<<256, 256>>>(ldt, lAr, Aim, C2);
    k_encoder<<<4096, 256>>>(x, ebr, ebi);
    for (int l = 0; l < NLc; ++l){
        k_scan<<<512, 128>>>(l, s4D);
        k_gemm<<<128, 256, 196608>>>(l, Wout, bout);
        k_combine<<<8192, 256>>>(l, gam, bet);
    }
    k_decoder<<<4096, 256>>>(dbr, dbi, out);
}